// round 4
// baseline (speedup 1.0000x reference)
#include <cuda_runtime.h>

// WaveLetPooling: input (8, 512, 512, 64) fp32 NHWC.
// Output: [ll | lh | hl | hh], each (8, 256, 256, 64), concatenated in d_out.
//
// Persistent grid-stride variant: grid sized to exactly one wave
// (148 SMs x 4 CTAs of 512 threads), each thread loops over the index
// space. Removes all wave-transition bubbles; loop iterations overlap
// loads of i+1 with stores of i for continuous DRAM occupancy.

#define N_  8u
#define H_  512u
#define W_  512u
#define C_  64u
#define HO  (H_/2u)       // 256
#define WO  (W_/2u)       // 256
#define C4  (C_/4u)       // 16 float4 per position
#define Q4  (N_*HO*WO*C4) // float4 per quadrant = 8,388,608

#define BLOCK  512u
#define GRID   (148u * 4u)   // one full wave on GB300 (152 SMs; 148 keeps B300 parity)

__device__ __forceinline__ float4 f4add(const float4& x, const float4& y) {
    return make_float4(x.x + y.x, x.y + y.y, x.z + y.z, x.w + y.w);
}
__device__ __forceinline__ float4 f4sub(const float4& x, const float4& y) {
    return make_float4(x.x - y.x, x.y - y.y, x.z - y.z, x.w - y.w);
}
__device__ __forceinline__ float4 f4half(const float4& x) {
    return make_float4(0.5f * x.x, 0.5f * x.y, 0.5f * x.z, 0.5f * x.w);
}

__global__ __launch_bounds__(BLOCK) void wavelet_pool_kernel(
    const float4* __restrict__ in, float4* __restrict__ out)
{
    const unsigned stride = GRID * BLOCK;          // 303,104
    const unsigned ROW4 = W_ * C4;                 // 8192

    for (unsigned tid = blockIdx.x * BLOCK + threadIdx.x; tid < Q4; tid += stride) {
        // tid -> (n, ho, wo, c4)
        unsigned c4 = tid & 15u;
        unsigned wo = (tid >> 4) & 255u;
        unsigned ho = (tid >> 12) & 255u;
        unsigned n  = tid >> 20;

        unsigned ibase = ((n * H_ + 2u * ho) * W_ + 2u * wo) * C4 + c4;

        float4 a = in[ibase];
        float4 b = in[ibase + C4];
        float4 c = in[ibase + ROW4];
        float4 d = in[ibase + ROW4 + C4];

        // butterfly
        float4 s0 = f4add(a, b);
        float4 d0 = f4sub(b, a);
        float4 s1 = f4add(c, d);
        float4 d1 = f4sub(d, c);

        float4 ll = f4half(f4add(s0, s1));  //  a+b+c+d
        float4 lh = f4half(f4add(d0, d1));  // -a+b-c+d
        float4 hl = f4half(f4sub(s1, s0));  // -a-b+c+d
        float4 hh = f4half(f4sub(d1, d0));  //  a-b-c+d

        unsigned o = ((n * HO + ho) * WO + wo) * C4 + c4;
        __stcs(out + o,          ll);
        __stcs(out + o + Q4,     lh);
        __stcs(out + o + 2u*Q4,  hl);
        __stcs(out + o + 3u*Q4,  hh);
    }
}

extern "C" void kernel_launch(void* const* d_in, const int* in_sizes, int n_in,
                              void* d_out, int out_size)
{
    const float4* in  = (const float4*)d_in[0];
    float4*       out = (float4*)d_out;
    wavelet_pool_kernel<<<GRID, BLOCK>>>(in, out);
}

// round 5
// speedup vs baseline: 1.0998x; 1.0998x over previous
#include <cuda_runtime.h>

// WaveLetPooling: input (8, 512, 512, 64) fp32 NHWC.
// Output: [ll | lh | hl | hh], each (8, 256, 256, 64), concatenated in d_out.
//
// Final shape (evidence-driven): flat grid, one float4 of channels per
// thread (best DRAM% measured: 86.2%), 256-thread blocks, plain ld/st
// (default caching beat .cs hints), butterfly-factored Haar (12 ops vs
// 16 FFMA per float4 — fewer issue slots competing with LSU).

#define N_  8u
#define H_  512u
#define W_  512u
#define C_  64u
#define HO  (H_/2u)       // 256
#define WO  (W_/2u)       // 256
#define C4  (C_/4u)       // 16 float4 per position
#define Q4  (N_*HO*WO*C4) // float4 per quadrant = 8,388,608

__device__ __forceinline__ float4 f4add(const float4& x, const float4& y) {
    return make_float4(x.x + y.x, x.y + y.y, x.z + y.z, x.w + y.w);
}
__device__ __forceinline__ float4 f4sub(const float4& x, const float4& y) {
    return make_float4(x.x - y.x, x.y - y.y, x.z - y.z, x.w - y.w);
}
__device__ __forceinline__ float4 f4half(const float4& x) {
    return make_float4(0.5f * x.x, 0.5f * x.y, 0.5f * x.z, 0.5f * x.w);
}

__global__ __launch_bounds__(256) void wavelet_pool_kernel(
    const float4* __restrict__ in, float4* __restrict__ out)
{
    unsigned tid = blockIdx.x * blockDim.x + threadIdx.x;
    // tid -> (n, ho, wo, c4)
    unsigned c4 = tid & 15u;
    unsigned wo = (tid >> 4) & 255u;
    unsigned ho = (tid >> 12) & 255u;
    unsigned n  = tid >> 20;

    unsigned ibase = ((n * H_ + 2u * ho) * W_ + 2u * wo) * C4 + c4;
    const unsigned ROW4 = W_ * C4;  // 8192 float4 per input row

    float4 a = in[ibase];
    float4 b = in[ibase + C4];
    float4 c = in[ibase + ROW4];
    float4 d = in[ibase + ROW4 + C4];

    // butterfly: s0=a+b, d0=b-a, s1=c+d, d1=d-c
    float4 s0 = f4add(a, b);
    float4 d0 = f4sub(b, a);
    float4 s1 = f4add(c, d);
    float4 d1 = f4sub(d, c);

    float4 ll = f4half(f4add(s0, s1));  //  a+b+c+d
    float4 lh = f4half(f4add(d0, d1));  // -a+b-c+d
    float4 hl = f4half(f4sub(s1, s0));  // -a-b+c+d
    float4 hh = f4half(f4sub(d1, d0));  //  a-b-c+d

    unsigned o = ((n * HO + ho) * WO + wo) * C4 + c4;
    out[o]         = ll;
    out[o + Q4]    = lh;
    out[o + 2u*Q4] = hl;
    out[o + 3u*Q4] = hh;
}

extern "C" void kernel_launch(void* const* d_in, const int* in_sizes, int n_in,
                              void* d_out, int out_size)
{
    const float4* in  = (const float4*)d_in[0];
    float4*       out = (float4*)d_out;

    const unsigned total = Q4;             // 8,388,608 threads
    const unsigned block = 256;
    const unsigned grid  = total / block;  // 32768
    wavelet_pool_kernel<<<grid, block>>>(in, out);
}

// round 6
// speedup vs baseline: 1.1027x; 1.0026x over previous
#include <cuda_runtime.h>

// WaveLetPooling: input (8, 512, 512, 64) fp32 NHWC.
// a = in[:,0::2,0::2,:], b = in[:,0::2,1::2,:], c = in[:,1::2,0::2,:], d = in[:,1::2,1::2,:]
// ll = .5(a+b+c+d); lh = .5(-a+b-c+d); hl = .5(-a-b+c+d); hh = .5(a-b-c+d)
// Output: [ll | lh | hl | hh], each (8, 256, 256, 64), concatenated in d_out.
//
// FINAL (roofline-converged): pure streaming kernel, HBM-bound at
// ~6.8 TB/s (86% of spec, the achieved ceiling for a 1:1 R/W mix).
// Best measured configuration across 5 profiled variants: flat grid,
// one float4 of channels per thread, 256-thread blocks, default-cached
// loads/stores, FFMA form (FFMA-imm issues at rt=1 per SMSP).

#define N_  8u
#define H_  512u
#define W_  512u
#define C_  64u
#define HO  (H_/2u)       // 256
#define WO  (W_/2u)       // 256
#define C4  (C_/4u)       // 16 float4 per position
#define Q4  (N_*HO*WO*C4) // float4 count per quadrant = 8,388,608

__global__ __launch_bounds__(256) void wavelet_pool_kernel(
    const float4* __restrict__ in, float4* __restrict__ out)
{
    unsigned tid = blockIdx.x * blockDim.x + threadIdx.x;
    // tid -> (n, ho, wo, c4): c4 in [0,16), wo in [0,256), ho in [0,256), n in [0,8)
    unsigned c4 = tid & 15u;
    unsigned wo = (tid >> 4) & 255u;
    unsigned ho = (tid >> 12) & 255u;
    unsigned n  = tid >> 20;

    // input float4 index: ((n*H + h)*W + w)*C4 + c4, with h=2*ho, w=2*wo
    unsigned ibase = ((n * H_ + 2u * ho) * W_ + 2u * wo) * C4 + c4;
    const unsigned ROW4 = W_ * C4;  // float4 per input row = 8192

    float4 a = in[ibase];
    float4 b = in[ibase + C4];
    float4 c = in[ibase + ROW4];
    float4 d = in[ibase + ROW4 + C4];

    float4 ll, lh, hl, hh;
    ll.x = 0.5f * ( a.x + b.x + c.x + d.x);
    ll.y = 0.5f * ( a.y + b.y + c.y + d.y);
    ll.z = 0.5f * ( a.z + b.z + c.z + d.z);
    ll.w = 0.5f * ( a.w + b.w + c.w + d.w);

    lh.x = 0.5f * (-a.x + b.x - c.x + d.x);
    lh.y = 0.5f * (-a.y + b.y - c.y + d.y);
    lh.z = 0.5f * (-a.z + b.z - c.z + d.z);
    lh.w = 0.5f * (-a.w + b.w - c.w + d.w);

    hl.x = 0.5f * (-a.x - b.x + c.x + d.x);
    hl.y = 0.5f * (-a.y - b.y + c.y + d.y);
    hl.z = 0.5f * (-a.z - b.z + c.z + d.z);
    hl.w = 0.5f * (-a.w - b.w + c.w + d.w);

    hh.x = 0.5f * ( a.x - b.x - c.x + d.x);
    hh.y = 0.5f * ( a.y - b.y - c.y + d.y);
    hh.z = 0.5f * ( a.z - b.z - c.z + d.z);
    hh.w = 0.5f * ( a.w - b.w - c.w + d.w);

    // output float4 index within a quadrant: ((n*HO + ho)*WO + wo)*C4 + c4
    unsigned o = ((n * HO + ho) * WO + wo) * C4 + c4;
    out[o]          = ll;
    out[o + Q4]     = lh;
    out[o + 2u*Q4]  = hl;
    out[o + 3u*Q4]  = hh;
}

extern "C" void kernel_launch(void* const* d_in, const int* in_sizes, int n_in,
                              void* d_out, int out_size)
{
    const float4* in  = (const float4*)d_in[0];
    float4*       out = (float4*)d_out;

    const unsigned total = Q4;             // 8,388,608 threads
    const unsigned block = 256;
    const unsigned grid  = total / block;  // 32768
    wavelet_pool_kernel<<<grid, block>>>(in, out);
}